// round 1
// baseline (speedup 1.0000x reference)
#include <cuda_runtime.h>
#include <cstdint>

#define H 64

// ---- packed f32x2 helpers (FFMA2 is PTX-only on sm_103a) ----
__device__ __forceinline__ unsigned long long pack2(float a, float b){
    unsigned long long v;
    asm("mov.b64 %0, {%1, %2};" : "=l"(v) : "f"(a), "f"(b));
    return v;
}
__device__ __forceinline__ void unpack2(unsigned long long v, float &a, float &b){
    asm("mov.b64 {%0, %1}, %2;" : "=f"(a), "=f"(b) : "l"(v));
}
__device__ __forceinline__ void fma2(unsigned long long &d, unsigned long long a, unsigned long long b){
    asm("fma.rn.f32x2 %0, %1, %2, %0;" : "+l"(d) : "l"(a), "l"(b));
}

// ELU with fast exp (rel err ~1e-7, far below 1e-3 tolerance)
__device__ __forceinline__ float elu(float x){
    return x > 0.f ? x : (__expf(x) - 1.f);
}

__global__ __launch_bounds__(128)
void odefunc_kernel(const float* __restrict__ zlp,
                    const float* __restrict__ W1, const float* __restrict__ b1,
                    const float* __restrict__ W2, const float* __restrict__ b2,
                    const float* __restrict__ W3, const float* __restrict__ b3,
                    float* __restrict__ out, int B)
{
    // W2 row-major (64,64). M[k,j] = W2[k,j] * C[j,k], C = W1 @ W3 (64x64).
    __shared__ __align__(16) float sW2[H*H];
    __shared__ __align__(16) float sM [H*H];
    __shared__ float sB1[H], sB2[H], sRS[H];
    __shared__ float sW1[2*H];   // W1 row-major (64,2)
    __shared__ float sW3[2*H];   // W3 row-major (2,64)
    __shared__ float sB3[2];

    const int tid = threadIdx.x;

    for (int i = tid; i < H; i += blockDim.x){ sB1[i] = b1[i]; sB2[i] = b2[i]; }
    for (int i = tid; i < 2*H; i += blockDim.x){ sW1[i] = W1[i]; sW3[i] = W3[i]; }
    if (tid < 2) sB3[tid] = b3[tid];

    // Build sW2 and the fused trace matrix sM (reads global W1/W3 directly; cached)
    for (int idx = tid; idx < H*H; idx += blockDim.x){
        int k = idx >> 6, j = idx & 63;
        float w2 = W2[idx];
        sW2[idx] = w2;
        float c = fmaf(W1[2*j], W3[k], W1[2*j+1] * W3[H+k]);   // C[j][k]
        sM[idx] = w2 * c;
    }
    __syncthreads();

    // Row-sums of M: t_k = rs[k] + sum_j M[k,j]*min(h1[j],0)   (since elu' = 1+min(h,0))
    if (tid < H){
        float s = 0.f;
        #pragma unroll 8
        for (int j = 0; j < H; j++) s += sM[tid*H + j];
        sRS[tid] = s;
    }
    __syncthreads();

    const float b30 = sB3[0], b31 = sB3[1];
    const int stride = gridDim.x * blockDim.x;

    for (int i = blockIdx.x * blockDim.x + tid; i < B; i += stride){
        const float z0 = zlp[3*i], z1 = zlp[3*i + 1];

        // Layer 1: h1 = elu(W1 z + b1), packed pairs; m1 = min(h1,0) packed
        unsigned long long hh[H/2], mm[H/2];
        #pragma unroll
        for (int jj = 0; jj < H/2; jj++){
            int j0 = 2*jj, j1 = 2*jj + 1;
            float a0 = fmaf(sW1[2*j0], z0, fmaf(sW1[2*j0+1], z1, sB1[j0]));
            float a1 = fmaf(sW1[2*j1], z0, fmaf(sW1[2*j1+1], z1, sB1[j1]));
            float h0 = elu(a0), h1v = elu(a1);
            hh[jj] = pack2(h0, h1v);
            mm[jj] = pack2(fminf(h0, 0.f), fminf(h1v, 0.f));
        }

        // Layer 2 + output + trace, fused over k. Two packed dot products per k.
        float o0 = 0.f, o1 = 0.f, tr = 0.f;
        #pragma unroll 1
        for (int k = 0; k < H; k++){
            const ulonglong2* w2row = reinterpret_cast<const ulonglong2*>(&sW2[k*H]);
            const ulonglong2* mrow  = reinterpret_cast<const ulonglong2*>(&sM [k*H]);
            unsigned long long accA = 0ull, accB = 0ull, tA = 0ull, tB = 0ull;
            #pragma unroll
            for (int q = 0; q < 16; q++){
                ulonglong2 w = w2row[q];
                fma2(accA, w.x, hh[2*q]);
                fma2(accB, w.y, hh[2*q+1]);
                ulonglong2 m = mrow[q];
                fma2(tA, m.x, mm[2*q]);
                fma2(tB, m.y, mm[2*q+1]);
            }
            float x0, x1, y0, y1;
            unpack2(accA, x0, x1); unpack2(accB, y0, y1);
            float a2 = (x0 + x1) + (y0 + y1) + sB2[k];
            float h2 = elu(a2);
            o0 = fmaf(sW3[k],   h2, o0);
            o1 = fmaf(sW3[H+k], h2, o1);
            unpack2(tA, x0, x1); unpack2(tB, y0, y1);
            float tk = (x0 + x1) + (y0 + y1) + sRS[k];
            float g2 = 1.f + fminf(h2, 0.f);
            tr = fmaf(g2, tk, tr);
        }

        out[3*i]     = o0 + b30;
        out[3*i + 1] = o1 + b31;
        out[3*i + 2] = -tr;
    }
}

extern "C" void kernel_launch(void* const* d_in, const int* in_sizes, int n_in,
                              void* d_out, int out_size)
{
    // metadata order: t, z_and_logp, W1, b1, W2, b2, W3, b3
    const float* zlp = (const float*)d_in[1];
    const float* W1  = (const float*)d_in[2];
    const float* b1  = (const float*)d_in[3];
    const float* W2  = (const float*)d_in[4];
    const float* b2  = (const float*)d_in[5];
    const float* W3  = (const float*)d_in[6];
    const float* b3  = (const float*)d_in[7];
    float* out = (float*)d_out;
    int B = in_sizes[1] / 3;

    const int block = 128;
    const int grid  = 1480;   // grid-stride; ~5.3 samples/thread, weight-load amortized
    odefunc_kernel<<<grid, block>>>(zlp, W1, b1, W2, b2, W3, b3, out, B);
}